// round 12
// baseline (speedup 1.0000x reference)
#include <cuda_runtime.h>

// Positional encoding: out[n, c, {sin,cos}, d] = trig(x[n,c] * 2^d), d=0..9, c=0..2.
// Row = 60 f32 = 15 float4 slots. Block-chunked layout: each block owns a
// CONTIGUOUS range of output slots and sweeps it with inner stride = blockDim
// (480, a multiple of 15 so the slot decomposition tid%15 stays loop-invariant).
// This turns the store pattern into ~592 sequential write streams (7.7KB steps)
// instead of grid-stride's scattered 4MB-apart stores -> DRAM row locality.

#define HALF_PI 1.57079632679489662f
#define TPB 480   // threads per block; 480 % 15 == 0

__global__ void __launch_bounds__(TPB) pe_kernel(const float* __restrict__ x,
                                                 float4* __restrict__ out,
                                                 int total /* N*15 */,
                                                 int chunk /* slots per block, %480==0 */) {
    int start = blockIdx.x * chunk;          // start % 15 == 0 (chunk % 15 == 0)
    int end = min(start + chunk, total);
    int t0 = start + threadIdx.x;

    // Loop-invariant slot decomposition (inner stride TPB % 15 == 0).
    int k = threadIdx.x % 15;  // float4 slot within row
    int c = k / 5;             // channel 0..2
    int j = k - c * 5;         // float4 within channel block

    float scale[4], off[4];
#pragma unroll
    for (int m = 0; m < 4; ++m) {
        int r = 4 * j + m;              // 0..19 within channel block
        int iscos = (r >= 10) ? 1 : 0;  // first 10 sin, last 10 cos
        int d = r - 10 * iscos;         // frequency exponent 0..9
        scale[m] = __int_as_float((127 + d) << 23);  // exact 2^d
        off[m] = iscos ? HALF_PI : 0.0f;             // cos(p) = sin(p + pi/2)
    }

    int xi = (t0 / 15) * 3 + c;          // x index for first slot
    const int xstep = (TPB / 15) * 3;    // = 96: x advance per iteration

    for (int t = t0; t < end; t += TPB, xi += xstep) {
        float xv = __ldg(&x[xi]);
        float4 v;
        v.x = __sinf(fmaf(xv, scale[0], off[0]));
        v.y = __sinf(fmaf(xv, scale[1], off[1]));
        v.z = __sinf(fmaf(xv, scale[2], off[2]));
        v.w = __sinf(fmaf(xv, scale[3], off[3]));
        __stcs(&out[t], v);   // streaming store: don't pollute L2 with 480MB
    }
}

extern "C" void kernel_launch(void* const* d_in, const int* in_sizes, int n_in,
                              void* d_out, int out_size) {
    const float* x = (const float*)d_in[0];
    float4* out = (float4*)d_out;
    int n_rows = in_sizes[0] / 3;   // x is [N, 3]
    int total = n_rows * 15;        // float4 slots

    // 592 blocks = 4/SM * 148 SMs at 480 threads -> 1920 thr/SM (94% occ).
    const int blocks = 592;
    // chunk: slots per block, rounded up to a multiple of TPB (and thus of 15).
    long long per = ((long long)total + blocks - 1) / blocks;
    int chunk = (int)(((per + TPB - 1) / TPB) * TPB);
    pe_kernel<<<blocks, TPB>>>(x, out, total, chunk);
}